// round 13
// baseline (speedup 1.0000x reference)
#include <cuda_runtime.h>
#include <cstddef>

typedef unsigned long long u64;

// ---------------- scratch (no allocations allowed) ----------------
__device__ float g_Wf[3 * 256 * 256];   // folded QKV weights (scale folded into Wq')
__device__ float g_Wc[256 * 256];       // folded W1@Wao
__device__ float g_bf[768];             // folded QKV biases
__device__ float g_bc[256];             // folded W1@bao + b1
__device__ float g_q[4096 * 256];
__device__ float g_k[768 * 256];
__device__ float g_v[768 * 256];
__device__ float g_ctx[4096 * 256];
__device__ float g_fused[4096 * 256];
__device__ float g_h2[4096 * 128];

#define ATTN_SCALE 0.17677669529663687f   // 1/sqrt(32)

// ---------------- packed f32x2 helpers (sm_10x FFMA2) ----------------------
__device__ __forceinline__ void fma2(u64& d, u64 a, u64 b) {
    asm("fma.rn.f32x2 %0, %1, %2, %0;" : "+l"(d) : "l"(a), "l"(b));
}
__device__ __forceinline__ u64 dup2(float x) {
    u64 r; unsigned xi = __float_as_uint(x);
    asm("mov.b64 %0, {%1, %1};" : "=l"(r) : "r"(xi));
    return r;
}
__device__ __forceinline__ float2 unpack2(u64 v) {
    unsigned lo, hi;
    asm("mov.b64 {%0, %1}, %2;" : "=r"(lo), "=r"(hi) : "l"(v));
    return make_float2(__uint_as_float(lo), __uint_as_float(hi));
}

// ---------------- fast exp: magic-number round + 2^f poly (FMA pipe) ------
__device__ __forceinline__ float fast_exp(float x) {
    float t = x * 1.4426950408889634f;           // log2(e)
    t = fminf(fmaxf(t, -120.0f), 120.0f);
    float z = t + 12582912.0f;                   // round-to-nearest int
    int   n = __float_as_int(z) - 0x4B400000;
    float f = t - (z - 12582912.0f);             // f in [-0.5, 0.5]
    float p = 1.3333558146e-3f;
    p = fmaf(p, f, 9.6181291076e-3f);
    p = fmaf(p, f, 5.5504108664e-2f);
    p = fmaf(p, f, 2.4022650695e-1f);
    p = fmaf(p, f, 6.9314718056e-1f);
    p = fmaf(p, f, 1.0f);
    return __int_as_float((n + 127) << 23) * p;  // 2^n * 2^f
}

// ============================================================================
// f32x2 GEMM tile: C[bm:+128, bn:+64] = A[bm:, :K] @ W^T (+bias)(+relu)
// W is [N, K] row-major. 128 threads, 8x8 microtile as 4 m-pairs x 8 n.
// Double-buffered BK=16 stages. Requires K%16==0, M%128==0, N%64==0.
// ============================================================================
#define AS_PAD 132   // 132 floats/row: 16B-aligned, conflict-free transpose STS

template <bool RELU>
__device__ __forceinline__ void gemm128_tile(
    const float* __restrict__ A, const float* __restrict__ W,
    const float* __restrict__ bias, float* __restrict__ C,
    int K, int N, int bm, int bn)
{
    __shared__ float As[2][16][AS_PAD];  // As[buf][k][m] (m-major within row)
    __shared__ float Bs[2][16][64];      // Bs[buf][k][n]
    const int tid = threadIdx.x;         // 0..127
    const int tx  = tid & 7;             // n-thread: 8 cols of 8
    const int ty  = tid >> 3;            // m-thread: 16 rows of 8
    const int tm  = ty << 3;
    const int tn  = tx << 3;

    // A loader: 4 float4 per thread per stage (rows ar+32r, k-quad ak)
    const int ar = tid >> 2;             // 0..31
    const int ak = (tid & 3) << 2;       // 0,4,8,12
    // B loader: rows wn=tid&63, k-octet wk (2 float4)
    const int wn = tid & 63;             // 0..63
    const int wk = (tid >> 6) << 3;      // 0 or 8

    const float* A0 = A + (size_t)(bm + ar) * K + ak;
    const float* W0 = W + (size_t)(bn + wn) * K + wk;

    float4 apre[4], wpre[2];
    #pragma unroll
    for (int r = 0; r < 4; r++) apre[r] = *(const float4*)(A0 + (size_t)(r * 32) * K);
    wpre[0] = *(const float4*)(W0);
    wpre[1] = *(const float4*)(W0 + 4);

    // stage 0 fill
    #pragma unroll
    for (int r = 0; r < 4; r++) {
        const float* s = &apre[r].x;
        #pragma unroll
        for (int i = 0; i < 4; i++) As[0][ak + i][ar + r * 32] = s[i];
    }
    #pragma unroll
    for (int i = 0; i < 4; i++) { Bs[0][wk + i][wn] = (&wpre[0].x)[i];
                                  Bs[0][wk + 4 + i][wn] = (&wpre[1].x)[i]; }
    __syncthreads();

    u64 acc[4][8];
    #pragma unroll
    for (int p = 0; p < 4; p++)
        #pragma unroll
        for (int j = 0; j < 8; j++) acc[p][j] = 0ull;   // = (0.0f, 0.0f)

    const int nk = K >> 4;
    int buf = 0;
    for (int s = 0; s < nk; s++) {
        if (s + 1 < nk) {   // prefetch next stage into regs
            #pragma unroll
            for (int r = 0; r < 4; r++)
                apre[r] = *(const float4*)(A0 + (size_t)(r * 32) * K + (s + 1) * 16);
            wpre[0] = *(const float4*)(W0 + (s + 1) * 16);
            wpre[1] = *(const float4*)(W0 + (s + 1) * 16 + 4);
        }
        #pragma unroll
        for (int kk = 0; kk < 16; kk++) {
            // A pairs come pre-packed straight out of shared memory
            ulonglong2 a01 = *(const ulonglong2*)(&As[buf][kk][tm]);
            ulonglong2 a23 = *(const ulonglong2*)(&As[buf][kk][tm + 4]);
            float4 w0 = *(const float4*)(&Bs[buf][kk][tn]);
            float4 w1 = *(const float4*)(&Bs[buf][kk][tn + 4]);
            u64 wd[8] = {dup2(w0.x), dup2(w0.y), dup2(w0.z), dup2(w0.w),
                         dup2(w1.x), dup2(w1.y), dup2(w1.z), dup2(w1.w)};
            #pragma unroll
            for (int j = 0; j < 8; j++) {
                fma2(acc[0][j], a01.x, wd[j]);
                fma2(acc[1][j], a01.y, wd[j]);
                fma2(acc[2][j], a23.x, wd[j]);
                fma2(acc[3][j], a23.y, wd[j]);
            }
        }
        if (s + 1 < nk) {
            int nb = buf ^ 1;
            #pragma unroll
            for (int r = 0; r < 4; r++) {
                const float* sp = &apre[r].x;
                #pragma unroll
                for (int i = 0; i < 4; i++) As[nb][ak + i][ar + r * 32] = sp[i];
            }
            #pragma unroll
            for (int i = 0; i < 4; i++) { Bs[nb][wk + i][wn] = (&wpre[0].x)[i];
                                          Bs[nb][wk + 4 + i][wn] = (&wpre[1].x)[i]; }
            buf = nb;
        }
        __syncthreads();
    }

    float bv[8];
    #pragma unroll
    for (int j = 0; j < 8; j++) bv[j] = bias[bn + tn + j];
    #pragma unroll
    for (int p = 0; p < 4; p++) {
        float lo[8], hi[8];
        #pragma unroll
        for (int j = 0; j < 8; j++) {
            float2 f = unpack2(acc[p][j]);
            lo[j] = f.x + bv[j];
            hi[j] = f.y + bv[j];
            if (RELU) { lo[j] = fmaxf(lo[j], 0.0f); hi[j] = fmaxf(hi[j], 0.0f); }
        }
        float* c0 = C + (size_t)(bm + tm + 2 * p) * N + bn + tn;
        float* c1 = c0 + N;
        *(float4*)(c0)     = make_float4(lo[0], lo[1], lo[2], lo[3]);
        *(float4*)(c0 + 4) = make_float4(lo[4], lo[5], lo[6], lo[7]);
        *(float4*)(c1)     = make_float4(hi[0], hi[1], hi[2], hi[3]);
        *(float4*)(c1 + 4) = make_float4(hi[4], hi[5], hi[6], hi[7]);
    }
}

template <bool RELU>
__global__ __launch_bounds__(128, 3) void gemm128_kernel(
    const float* __restrict__ A, const float* __restrict__ W,
    const float* __restrict__ bias, float* __restrict__ C, int N, int K)
{
    gemm128_tile<RELU>(A, W, bias, C, K, N, blockIdx.y * 128, blockIdx.x * 64);
}

// ---------------- merged QKV projection (176 blocks) ----------------------
__global__ __launch_bounds__(128, 3) void qkv_kernel(
    const float* __restrict__ spatial, const float* __restrict__ temporal,
    const float* __restrict__ Wf, const float* __restrict__ bf,
    float* __restrict__ q, float* __restrict__ k, float* __restrict__ v)
{
    int bid = blockIdx.x;
    const float* A; const float* W; const float* bias; float* C;
    int bx, by;
    if (bid < 128) {                      // q: 32 m-tiles x 4 n-tiles
        A = spatial;  W = Wf;           bias = bf;       C = q;
        bx = bid & 3; by = bid >> 2;
    } else if (bid < 152) {               // k: 6 x 4
        int t = bid - 128;
        A = temporal; W = Wf + 65536;   bias = bf + 256; C = k;
        bx = t & 3;   by = t >> 2;
    } else {                              // v: 6 x 4
        int t = bid - 152;
        A = temporal; W = Wf + 131072;  bias = bf + 512; C = v;
        bx = t & 3;   by = t >> 2;
    }
    gemm128_tile<false>(A, W, bias, C, 256, 256, by * 128, bx * 64);
}

// ============================================================================
// fold path: 64x64x16 scalar tile (proven; runs once per launch, 72 blocks)
// ============================================================================
__device__ __forceinline__ void fold_tile(
    const float* __restrict__ A, const float* __restrict__ W,
    float* __restrict__ C, int K, int N, int bm, int bn, float oscale)
{
    __shared__ float As[2][16][64];
    __shared__ float Bs[2][16][64];
    const int tid = threadIdx.x;
    const int tm = (tid >> 4) << 2;
    const int tn = (tid & 15) << 2;
    const int am = tid >> 2, ak = (tid & 3) << 2;      // A loader
    const int wkk = tid >> 4, wn4 = (tid & 15) << 2;   // W[K,N] loader

    const float* Arow = A + (size_t)(bm + am) * K + ak;
    float4 ap = *(const float4*)Arow;
    float4 wp = *(const float4*)(W + (size_t)wkk * N + bn + wn4);

    As[0][ak + 0][am] = ap.x; As[0][ak + 1][am] = ap.y;
    As[0][ak + 2][am] = ap.z; As[0][ak + 3][am] = ap.w;
    *(float4*)&Bs[0][wkk][wn4] = wp;
    __syncthreads();

    float acc[4][4] = {};
    const int nk = K >> 4;
    int buf = 0;
    for (int s = 0; s < nk; s++) {
        if (s + 1 < nk) {
            ap = *(const float4*)(Arow + (s + 1) * 16);
            wp = *(const float4*)(W + (size_t)((s + 1) * 16 + wkk) * N + bn + wn4);
        }
        #pragma unroll
        for (int kk = 0; kk < 16; kk++) {
            float4 a4 = *(const float4*)(&As[buf][kk][tm]);
            float4 w4 = *(const float4*)(&Bs[buf][kk][tn]);
            float a[4] = {a4.x, a4.y, a4.z, a4.w};
            float w[4] = {w4.x, w4.y, w4.z, w4.w};
            #pragma unroll
            for (int i = 0; i < 4; i++)
                #pragma unroll
                for (int j = 0; j < 4; j++)
                    acc[i][j] = fmaf(a[i], w[j], acc[i][j]);
        }
        if (s + 1 < nk) {
            int nb = buf ^ 1;
            As[nb][ak + 0][am] = ap.x; As[nb][ak + 1][am] = ap.y;
            As[nb][ak + 2][am] = ap.z; As[nb][ak + 3][am] = ap.w;
            *(float4*)&Bs[nb][wkk][wn4] = wp;
            buf = nb;
        }
        __syncthreads();
    }

    #pragma unroll
    for (int i = 0; i < 4; i++) {
        float4 r;
        float* pr = &r.x;
        #pragma unroll
        for (int j = 0; j < 4; j++) pr[j] = acc[i][j] * oscale;
        *(float4*)(C + (size_t)(bm + tm + i) * N + bn + tn) = r;
    }
}

// blocks [0,48):  Wf = Win @ (Ws | Wt), q-rows (<256) scaled by ATTN_SCALE
// blocks [48,64): Wc = W1 @ Wao
// blocks [64,72): biases bf[768] (q part scaled), bc[256]
__global__ __launch_bounds__(256) void fold_kernel(
    const float* __restrict__ Win, const float* __restrict__ Ws,
    const float* __restrict__ Wt,  const float* __restrict__ W1,
    const float* __restrict__ Wao,
    const float* __restrict__ bin, const float* __restrict__ bs,
    const float* __restrict__ bt,  const float* __restrict__ bao,
    const float* __restrict__ b1,
    float* __restrict__ Wf, float* __restrict__ Wc,
    float* __restrict__ bf, float* __restrict__ bc)
{
    int bid = blockIdx.x;
    if (bid < 48) {
        int mt = bid >> 2, nt = bid & 3;
        const float* W = (mt < 4) ? Ws : Wt;
        float osc = (mt < 4) ? ATTN_SCALE : 1.0f;
        fold_tile(Win, W, Wf, 256, 256, mt * 64, nt * 64, osc);
    } else if (bid < 64) {
        int t = bid - 48, mt = t >> 2, nt = t & 3;
        fold_tile(W1, Wao, Wc, 256, 256, mt * 64, nt * 64, 1.0f);
    } else {
        int w = (bid - 64) * 8 + (threadIdx.x >> 5);
        int lane = threadIdx.x & 31;
        for (int rep = 0; rep < 16; rep++) {
            int o = w * 16 + rep;
            const float* row; const float* src; float add, scl; float* dst; int oi;
            if (o < 768) {
                row = Win + (size_t)o * 256;
                src = (o < 256) ? bs : bt;
                add = bin[o]; dst = bf; oi = o;
                scl = (o < 256) ? ATTN_SCALE : 1.0f;
            } else {
                int o2 = o - 768;
                row = W1 + (size_t)o2 * 256;
                src = bao; add = b1[o2]; dst = bc; oi = o2; scl = 1.0f;
            }
            float p = 0.0f;
            #pragma unroll
            for (int kk = 0; kk < 256; kk += 32)
                p = fmaf(row[kk + lane], src[kk + lane], p);
            #pragma unroll
            for (int off = 16; off; off >>= 1)
                p += __shfl_xor_sync(0xffffffffu, p, off);
            if (lane == 0) dst[oi] = (add + p) * scl;
        }
    }
}

// ---------------- attention: streaming softmax, f32x2 packed math ---------
// q pre-scaled. One thread per (b,h,n) row; grid (4, NH, B), 128 thr.
__global__ __launch_bounds__(128) void attn_kernel(
    const float* __restrict__ q, const float* __restrict__ k,
    const float* __restrict__ v, float* __restrict__ ctx)
{
    __shared__ float ks[96][32];
    __shared__ float vs[96][32];
    const int b = blockIdx.z, h = blockIdx.y;
    const size_t kvbase = (size_t)b * 96 * 256 + h * 32;
    for (int i = threadIdx.x; i < 96 * 8; i += 128) {
        int s = i >> 3, d4 = (i & 7) << 2;
        *(float4*)&ks[s][d4] = *(const float4*)(k + kvbase + (size_t)s * 256 + d4);
        *(float4*)&vs[s][d4] = *(const float4*)(v + kvbase + (size_t)s * 256 + d4);
    }
    __syncthreads();

    const int n = blockIdx.x * 128 + threadIdx.x;
    const u64* q2 = (const u64*)(q + (size_t)(b * 512 + n) * 256 + h * 32);
    u64 qp[16];
    #pragma unroll
    for (int p = 0; p < 16; p++) qp[p] = q2[p];

    u64 acc[16];
    #pragma unroll
    for (int p = 0; p < 16; p++) acc[p] = 0ull;
    float sum = 0.0f;

    #pragma unroll 2
    for (int s = 0; s < 96; s++) {
        const u64* krow = (const u64*)&ks[s][0];
        u64 d0 = 0ull, d1 = 0ull, d2 = 0ull, d3 = 0ull;
        #pragma unroll
        for (int p = 0; p < 16; p += 4) {
            fma2(d0, qp[p + 0], krow[p + 0]);
            fma2(d1, qp[p + 1], krow[p + 1]);
            fma2(d2, qp[p + 2], krow[p + 2]);
            fma2(d3, qp[p + 3], krow[p + 3]);
        }
        float2 f0 = unpack2(d0), f1 = unpack2(d1);
        float2 f2 = unpack2(d2), f3 = unpack2(d3);
        float logit = ((f0.x + f0.y) + (f1.x + f1.y))
                    + ((f2.x + f2.y) + (f3.x + f3.y));
        float e = fast_exp(logit);     // logits bounded; clamp inside fast_exp
        sum += e;
        u64 ed = dup2(e);
        const u64* vrow = (const u64*)&vs[s][0];
        #pragma unroll
        for (int p = 0; p < 16; p++) fma2(acc[p], ed, vrow[p]);
    }
    float inv = 1.0f / sum;

    float* crow = ctx + (size_t)(b * 512 + n) * 256 + h * 32;
    #pragma unroll
    for (int p = 0; p < 8; p++) {
        float2 fa = unpack2(acc[2 * p]);
        float2 fb = unpack2(acc[2 * p + 1]);
        *(float4*)(crow + p * 4) =
            make_float4(fa.x * inv, fa.y * inv, fb.x * inv, fb.y * inv);
    }
}

// ---------------- final: y = h2 @ Wo2^T + bo2, broadcast over S -----------
__global__ __launch_bounds__(256) void final_kernel(
    const float* __restrict__ h2, const float* __restrict__ Wo2,
    const float* __restrict__ bo2, float* __restrict__ out)
{
    int g = blockIdx.x * 256 + threadIdx.x;   // 0..16383
    int o = g & 3;
    int row = g >> 2;        // 0..4095
    int b = row >> 9;
    int n = row & 511;

    float acc = bo2[o];
    const float* hr = h2 + (size_t)row * 128;
    const float* wr = Wo2 + (size_t)o * 128;
    #pragma unroll 8
    for (int kk = 0; kk < 128; kk++) acc = fmaf(hr[kk], wr[kk], acc);

    float* base = out + (size_t)b * (96 * 512 * 4) + (size_t)n * 4 + o;
    #pragma unroll 4
    for (int s = 0; s < 96; s++) base[(size_t)s * 2048] = acc;
}

// ---------------- launch ----------------
extern "C" void kernel_launch(void* const* d_in, const int* in_sizes, int n_in,
                              void* d_out, int out_size)
{
    const float* spatial  = (const float*)d_in[0];   // [8,512,256]
    const float* temporal = (const float*)d_in[1];   // [8,96,256]
    const float* Ws_  = (const float*)d_in[2];       // [256,256]
    const float* bs_  = (const float*)d_in[3];
    const float* Wt_  = (const float*)d_in[4];
    const float* bt_  = (const float*)d_in[5];
    const float* Win  = (const float*)d_in[6];       // [768,256]
    const float* bin_ = (const float*)d_in[7];       // [768]
    const float* Wao  = (const float*)d_in[8];       // [256,256]
    const float* bao  = (const float*)d_in[9];
    const float* W1   = (const float*)d_in[10];      // [256,256]
    const float* b1   = (const float*)d_in[11];
    const float* Wo1  = (const float*)d_in[12];      // [128,256]
    const float* bo1  = (const float*)d_in[13];
    const float* Wo2  = (const float*)d_in[14];      // [4,128]
    const float* bo2  = (const float*)d_in[15];
    float* out = (float*)d_out;

    float *pWf, *pWc, *pbf, *pbc, *pq, *pk, *pv, *pctx, *pfused, *ph2;
    cudaGetSymbolAddress((void**)&pWf,    g_Wf);
    cudaGetSymbolAddress((void**)&pWc,    g_Wc);
    cudaGetSymbolAddress((void**)&pbf,    g_bf);
    cudaGetSymbolAddress((void**)&pbc,    g_bc);
    cudaGetSymbolAddress((void**)&pq,     g_q);
    cudaGetSymbolAddress((void**)&pk,     g_k);
    cudaGetSymbolAddress((void**)&pv,     g_v);
    cudaGetSymbolAddress((void**)&pctx,   g_ctx);
    cudaGetSymbolAddress((void**)&pfused, g_fused);
    cudaGetSymbolAddress((void**)&ph2,    g_h2);

    // 1) all folds: Wf (Win@Ws|Wt, scale folded), Wc (W1@Wao), bf, bc
    fold_kernel<<<72, 256>>>(Win, Ws_, Wt_, W1, Wao,
                             bin_, bs_, bt_, bao, b1,
                             pWf, pWc, pbf, pbc);
    // 2) q,k,v in one launch (q pre-scaled), f32x2 GEMM
    qkv_kernel<<<176, 128>>>(spatial, temporal, pWf, pbf, pq, pk, pv);
    // 3) attention -> ctx [4096,256]
    attn_kernel<<<dim3(4, 8, 8), 128>>>(pq, pk, pv, pctx);
    // 4) fused = relu(ctx @ Wc^T + bc)   (Wao+W1 folded)
    gemm128_kernel<true><<<dim3(4, 32), 128>>>(pctx,   pWc, pbc, pfused, 256, 256);
    // 5) h2 = relu(fused @ Wo1^T + bo1)  [4096,128]
    gemm128_kernel<true><<<dim3(2, 32), 128>>>(pfused, Wo1, bo1, ph2,    128, 256);
    // 6) y = h2 @ Wo2^T + bo2, broadcast to [8,96,512,4]
    final_kernel<<<64, 256>>>(ph2, Wo2, bo2, out);
}